// round 14
// baseline (speedup 1.0000x reference)
#include <cuda_runtime.h>
#include <cuda_bf16.h>
#include <math.h>
#include <stdint.h>

// Eikonal loss: persistent blocks, double-buffered cp.async.bulk pipeline.
// Block owns ~4.6 strips of 16 rows x 512 cols; copy for strip n+1 issued
// before waiting on strip n (latency fully hidden after prologue).
// (B,1,H,W) = (64,1,512,512) fp32 -> 1 fp32 scalar.

#define H 512
#define W 512
#define TROWS 16
#define PROWS (TROWS + 2)
#define TILE_F (PROWS * W)          // floats per buffer
#define TILE_BYTES (TILE_F * 4)     // 36864
#define THREADS 256
#define PBLOCKS 444                 // 148 SMs * 3
#define MAX_BLOCKS 4096

__device__ float2 g_part[MAX_BLOCKS];
__device__ unsigned int g_ticket;   // zero-init at load; last block resets it

__device__ __forceinline__ float sqrt_approx(float x) {
    float r;
    asm("sqrt.approx.f32 %0, %1;" : "=f"(r) : "f"(x));
    return r;
}

__device__ __forceinline__ uint32_t smem_u32(const void* p) {
    uint32_t a;
    asm("{ .reg .u64 t; cvta.to.shared.u64 t, %1; cvt.u32.u64 %0, t; }" : "=r"(a) : "l"(p));
    return a;
}

__device__ __forceinline__ void bulk_cp(uint32_t sdst, const float* src,
                                        uint32_t bytes, uint32_t mbar) {
    asm volatile(
        "cp.async.bulk.shared::cta.global.mbarrier::complete_tx::bytes [%0], [%1], %2, [%3];"
        :: "r"(sdst), "l"(src), "r"(bytes), "r"(mbar) : "memory");
}

// tid0: stage pred rows y-1..y+16 (edge-clamped) of strip s into buffer.
__device__ __forceinline__ void issue_copy(const float* __restrict__ pred,
                                           int s, uint32_t sdst, uint32_t mbar) {
    const int b = s >> 5;
    const int y = (s & 31) * TROWS;
    const float* p = pred + (size_t)b * (H * W);
    asm volatile("mbarrier.arrive.expect_tx.shared.b64 _, [%0], %1;"
                 :: "r"(mbar), "r"((uint32_t)TILE_BYTES) : "memory");
    if (y > 0 && y + TROWS < H) {
        bulk_cp(sdst, p + (size_t)(y - 1) * W, TILE_BYTES, mbar);
    } else if (y == 0) {
        bulk_cp(sdst, p, W * 4, mbar);                                     // dup row 0
        bulk_cp(sdst + W * 4, p, (PROWS - 1) * W * 4, mbar);               // rows 0..16
    } else {
        bulk_cp(sdst, p + (size_t)(y - 1) * W, (PROWS - 1) * W * 4, mbar); // rows y-1..510
        bulk_cp(sdst + (PROWS - 1) * W * 4, p + (size_t)(H - 1) * W, W * 4, mbar); // dup 511
    }
}

__device__ __forceinline__ void mbar_wait(uint32_t mbar, uint32_t parity) {
    asm volatile(
        "{\n\t.reg .pred q;\n\t"
        "WL_%=:\n\t"
        "mbarrier.try_wait.parity.acquire.cta.shared::cta.b64 q, [%0], %1, 0x989680;\n\t"
        "@q bra.uni WD_%=;\n\t"
        "bra.uni WL_%=;\n\t"
        "WD_%=:\n\t}"
        :: "r"(mbar), "r"(parity) : "memory");
}

// Row features (UNSCALED) from an SMEM row.
__device__ __forceinline__ void row_sd_s(const float* __restrict__ sp_row,
                                         int x, int lane,
                                         float* __restrict__ S,
                                         float* __restrict__ D) {
    float4 v = *(const float4*)(sp_row + x);
    float wl = __shfl_up_sync(0xFFFFFFFFu, v.w, 1);
    float wr = __shfl_down_sync(0xFFFFFFFFu, v.x, 1);
    if (lane == 0)  wl = (x == 0)     ? v.x : sp_row[x - 1];
    if (lane == 31) wr = (x + 4 >= W) ? v.w : sp_row[x + 4];
    D[0] = v.y - wl;
    D[1] = v.z - v.x;
    D[2] = v.w - v.y;
    D[3] = wr  - v.z;
    S[0] = fmaf(2.0f, v.x, wl  + v.y);
    S[1] = fmaf(2.0f, v.y, v.x + v.z);
    S[2] = fmaf(2.0f, v.z, v.y + v.w);
    S[3] = fmaf(2.0f, v.w, v.z + wr );
}

// mag = sqrt(gx_u^2 + gy_u^2 + 6.4e-7) * 0.125
__device__ __forceinline__ void out_row(const float* S0, const float* S2,
                                        const float* D0, const float* D1, const float* D2,
                                        float4 rr, float& lsum, int& lcnt) {
    const float rv[4] = {rr.x, rr.y, rr.z, rr.w};
    #pragma unroll
    for (int j = 0; j < 4; j++) {
        float gx = fmaf(2.0f, D1[j], D0[j] + D2[j]);
        float gy = S2[j] - S0[j];
        float g2 = fmaf(gx, gx, fmaf(gy, gy, 6.4e-7f));
        float viol = fabsf(fmaf(sqrt_approx(g2), 0.125f, -1.0f));
        if (rv[j] > 0.5f) {
            lsum += viol;
            lcnt++;
        }
    }
}

extern __shared__ float s_dyn[];    // 2 * TILE_F floats

__global__ void __launch_bounds__(THREADS) eik_fused_kernel(
    const float* __restrict__ pred,
    const float* __restrict__ reach,
    float* __restrict__ out,
    int nStrips, int nBlocks)
{
    __shared__ __align__(8) uint64_t s_mbar[2];
    __shared__ float s_sum[8];
    __shared__ float s_cnt[8];
    __shared__ bool s_last;

    const int tid  = threadIdx.x;
    const int lane = tid & 31;
    const int G    = gridDim.x;

    const uint32_t mb0 = smem_u32(&s_mbar[0]);
    const uint32_t mb1 = smem_u32(&s_mbar[1]);
    const uint32_t sd0 = smem_u32(s_dyn);
    const uint32_t sd1 = sd0 + TILE_BYTES;

    if (tid == 0) {
        asm volatile("mbarrier.init.shared.b64 [%0], 1;" :: "r"(mb0) : "memory");
        asm volatile("mbarrier.init.shared.b64 [%0], 1;" :: "r"(mb1) : "memory");
    }
    __syncthreads();

    // compute decomposition: thread = 4 cols x 8 rows
    const int cg   = tid & 127;
    const int half = tid >> 7;
    const int x    = cg * 4;
    const int o0   = half * 8;

    float lsum = 0.0f;
    int   lcnt = 0;

    // prologue: stage first strip
    if (blockIdx.x < nStrips && tid == 0)
        issue_copy(pred, blockIdx.x, sd0, mb0);

    int n = 0;
    for (int s = blockIdx.x; s < nStrips; s += G, n++) {
        const uint32_t curB  = (n & 1) ? sd1 : sd0;
        const uint32_t curM  = (n & 1) ? mb1 : mb0;
        const float* sp = s_dyn + (n & 1) * TILE_F;

        // issue next strip's copy into the other buffer (free since n-1 ended in syncthreads)
        const int sn = s + G;
        if (sn < nStrips && tid == 0)
            issue_copy(pred, sn, (n & 1) ? sd0 : sd1, (n & 1) ? mb0 : mb1);
        (void)curB;

        mbar_wait(curM, (n >> 1) & 1);

        // ---- compute this strip ----
        const int b = s >> 5;
        const int y = (s & 31) * TROWS;
        const float* r = reach + (size_t)b * (H * W);

        float S[3][4], D[3][4];
        row_sd_s(sp + (o0 + 0) * W, x, lane, S[0], D[0]);
        row_sd_s(sp + (o0 + 1) * W, x, lane, S[1], D[1]);

        float4 rq[2];
        rq[0] = __ldcs((const float4*)(r + (size_t)(y + o0 + 0) * W + x));
        rq[1] = __ldcs((const float4*)(r + (size_t)(y + o0 + 1) * W + x));

        #pragma unroll
        for (int i = 0; i < 8; i++) {
            row_sd_s(sp + (o0 + i + 2) * W, x, lane, S[(i + 2) % 3], D[(i + 2) % 3]);
            float4 rr = rq[i & 1];
            if (i < 6)
                rq[i & 1] = __ldcs((const float4*)(r + (size_t)(y + o0 + i + 2) * W + x));
            out_row(S[i % 3], S[(i + 2) % 3], D[i % 3], D[(i + 1) % 3], D[(i + 2) % 3],
                    rr, lsum, lcnt);
        }
        __syncthreads();   // buffer reusable
    }

    // ---- block reduction (8 warps) ----
    float fcnt = (float)lcnt;
    #pragma unroll
    for (int off = 16; off > 0; off >>= 1) {
        lsum += __shfl_down_sync(0xFFFFFFFFu, lsum, off);
        fcnt += __shfl_down_sync(0xFFFFFFFFu, fcnt, off);
    }
    const int wid = tid >> 5;
    if (lane == 0) { s_sum[wid] = lsum; s_cnt[wid] = fcnt; }
    __syncthreads();

    if (wid == 0) {
        lsum = (lane < 8) ? s_sum[lane] : 0.0f;
        fcnt = (lane < 8) ? s_cnt[lane] : 0.0f;
        #pragma unroll
        for (int off = 4; off > 0; off >>= 1) {
            lsum += __shfl_down_sync(0xFFFFFFFFu, lsum, off);
            fcnt += __shfl_down_sync(0xFFFFFFFFu, fcnt, off);
        }
        if (lane == 0) {
            g_part[blockIdx.x] = make_float2(lsum, fcnt);
            __threadfence();
            unsigned int prev = atomicAdd(&g_ticket, 1u);
            s_last = (prev == (unsigned int)(nBlocks - 1));
        }
    }
    __syncthreads();

    if (s_last) {
        float fs = 0.0f, fc = 0.0f;
        for (int i = tid; i < nBlocks; i += THREADS) {
            float2 v2 = g_part[i];
            fs += v2.x;
            fc += v2.y;
        }
        #pragma unroll
        for (int off = 16; off > 0; off >>= 1) {
            fs += __shfl_down_sync(0xFFFFFFFFu, fs, off);
            fc += __shfl_down_sync(0xFFFFFFFFu, fc, off);
        }
        if (lane == 0) { s_sum[wid] = fs; s_cnt[wid] = fc; }
        __syncthreads();
        if (tid == 0) {
            fs = 0.0f; fc = 0.0f;
            #pragma unroll
            for (int i = 0; i < 8; i++) { fs += s_sum[i]; fc += s_cnt[i]; }
            out[0] = fs / fmaxf(fc, 1.0f);
            g_ticket = 0;   // reset for next graph replay
        }
    }
}

extern "C" void kernel_launch(void* const* d_in, const int* in_sizes, int n_in,
                              void* d_out, int out_size) {
    const float* pred  = (const float*)d_in[0];
    const float* reach = (const float*)d_in[1];
    float* out = (float*)d_out;

    const int total   = in_sizes[0];            // B*H*W
    const int nStrips = total / (W * TROWS);    // 2048 for B=64

    int blocks = PBLOCKS;
    if (blocks > nStrips) blocks = nStrips;

    static int smem_set = 0;
    if (!smem_set) {
        cudaFuncSetAttribute(eik_fused_kernel,
                             cudaFuncAttributeMaxDynamicSharedMemorySize,
                             2 * TILE_BYTES);
        smem_set = 1;
    }

    eik_fused_kernel<<<blocks, THREADS, 2 * TILE_BYTES>>>(pred, reach, out,
                                                          nStrips, blocks);
}